// round 10
// baseline (speedup 1.0000x reference)
#include <cuda_runtime.h>
#include <cstdint>

#define K_DIM   784
#define H_DIM   1024
#define O_DIM   10
#define B_SIZE  128
#define T_STEPS 200
#define M_TOTAL (B_SIZE * T_STEPS)   // 25600
#define BETA    0.95f

#define BMg 128
#define BNg 128
#define BKg 16
#define KT  49                       // 49*16 = 784 exact

typedef unsigned long long ull;

__device__ float    g_cur1[(size_t)M_TOTAL * H_DIM];
__device__ unsigned g_spk[(size_t)M_TOTAL * (H_DIM / 32)];
__device__ float    g_cur2T[(size_t)O_DIM * M_TOTAL];

// ---------------- packed fp32x2 (sm_103a FFMA2) ----------------
__device__ __forceinline__ ull ffma2(ull a, ull b, ull c) {
    ull d;
    asm("fma.rn.f32x2 %0, %1, %2, %3;" : "=l"(d) : "l"(a), "l"(b), "l"(c));
    return d;
}
__device__ __forceinline__ ull pack2(float x, float y) {
    ull d; asm("mov.b64 %0, {%1, %2};" : "=l"(d) : "f"(x), "f"(y)); return d;
}
__device__ __forceinline__ void unpack2(ull v, float& x, float& y) {
    asm("mov.b64 {%0, %1}, %2;" : "=f"(x), "=f"(y) : "l"(v));
}

// ---------------------------------------------------------------------------
// GEMM1: cur1[M,H] = x[M,K] @ w1[H,K]^T + b1. Bitwise fp32 (strict k-seq FMA
// chain per output; bias once at end). 128 threads (8 tr x 16 tc), per-thread
// 16m x 8n, FFMA2 pairs along m.
//   As layout: word(k,m) = k*128 + p(m>>2)*4 + (m&3), p(c)=((c&3)<<3)|(c>>2)
//     -> reads (16 m at fixed k) are 4 contiguous LDS.128, conflict-free
//     -> loader lane l takes chunk c(l)=((l&7)<<2)|(l>>3): p(c(l))=l -> STS
//        is contiguous per warp, conflict-free
//   Bd: duplicated pairs (b,b) -> b-operand is a raw LDS.64 half, zero MOVs.
// ---------------------------------------------------------------------------
__global__ __launch_bounds__(128, 2) void gemm1_ffma2(
    const float* __restrict__ x, const float* __restrict__ w1,
    const float* __restrict__ bias)
{
    __shared__ float As[BKg * BMg];        // 8KB
    __shared__ float Bd[BKg * BNg * 2];    // 16KB (duplicated)

    const int tid  = threadIdx.x;
    const int lane = tid & 31;
    const int warp = tid >> 5;
    const int tr   = tid & 7;          // m-block: rows tr*16..tr*16+15
    const int tc   = tid >> 3;         // n-block: cols tc*8..tc*8+7
    const int bm   = blockIdx.y * BMg;
    const int bn   = blockIdx.x * BNg;

    // A loader: lane covers chunk c (4 rows), this warp covers k = warp*4..+3
    const int ac  = ((lane & 7) << 2) | (lane >> 3);   // chunk 0..31
    const int am0 = ac * 4;                            // first of 4 m-rows
    const int ak0 = warp * 4;                          // first of 4 k
    // B loader: thread = one n-row, all 16 k
    const int bnr = tid;                               // n 0..127

    const float* agp = x  + (size_t)(bm + am0) * K_DIM + ak0;
    const float* bgp = w1 + (size_t)(bn + bnr) * K_DIM;

    // prologue: stage tile 0
    float av[4][4];          // av[r][q] = A[am0+r][ak0+q]
    float bvv[16];           // bvv[k]  = B[bnr][k]
    {
        #pragma unroll
        for (int r = 0; r < 4; r++) {
            const float4 v = *(const float4*)(agp + (size_t)r * K_DIM);
            av[r][0] = v.x; av[r][1] = v.y; av[r][2] = v.z; av[r][3] = v.w;
        }
        #pragma unroll
        for (int i = 0; i < 4; i++) {
            const float4 v = *(const float4*)(bgp + i * 4);
            bvv[i*4+0] = v.x; bvv[i*4+1] = v.y; bvv[i*4+2] = v.z; bvv[i*4+3] = v.w;
        }
    }

    ull acc[8][8];
    #pragma unroll
    for (int i = 0; i < 8; i++)
        #pragma unroll
        for (int j = 0; j < 8; j++) acc[i][j] = 0ULL;

    for (int t = 0; t < KT; t++) {
        __syncthreads();                       // previous tile fully consumed
        // STS A: per k (q), 4 m-values -> one STS.128 at word (ak0+q)*128 + lane*4
        #pragma unroll
        for (int q = 0; q < 4; q++) {
            *(float4*)&As[(ak0 + q) * BMg + lane * 4] =
                make_float4(av[0][q], av[1][q], av[2][q], av[3][q]);
        }
        // STS B: duplicated pairs, contiguous STS.64 per warp
        #pragma unroll
        for (int k = 0; k < BKg; k++)
            *(ull*)&Bd[k * (BNg * 2) + bnr * 2] = pack2(bvv[k], bvv[k]);
        __syncthreads();

        // stage next tile (latency hidden under ~2k cycles of FFMA2)
        if (t + 1 < KT) {
            const int kc = (t + 1) * BKg;
            #pragma unroll
            for (int r = 0; r < 4; r++) {
                const float4 v = *(const float4*)(agp + (size_t)r * K_DIM + kc);
                av[r][0] = v.x; av[r][1] = v.y; av[r][2] = v.z; av[r][3] = v.w;
            }
            #pragma unroll
            for (int i = 0; i < 4; i++) {
                const float4 v = *(const float4*)(bgp + kc + i * 4);
                bvv[i*4+0] = v.x; bvv[i*4+1] = v.y; bvv[i*4+2] = v.z; bvv[i*4+3] = v.w;
            }
        }

        #pragma unroll
        for (int k = 0; k < BKg; k++) {
            // A: 4 LDS.128 -> 8 natural m-pairs; read chunks i*8+tr contiguous
            ull ap[8];
            #pragma unroll
            for (int i = 0; i < 4; i++) {
                const ulonglong2 a2 =
                    *(const ulonglong2*)&As[k * BMg + (i * 8 + tr) * 4];
                ap[i * 2]     = a2.x;     // rows tr*16+i*4+0,1
                ap[i * 2 + 1] = a2.y;     // rows tr*16+i*4+2,3
            }
            // B: 4 LDS.128 (octet-broadcast) -> 8 duplicated pairs
            const float* bk = &Bd[k * (BNg * 2) + tc * 16];
            const ulonglong2 b0 = *(const ulonglong2*)(bk);
            const ulonglong2 b1 = *(const ulonglong2*)(bk + 4);
            const ulonglong2 b2 = *(const ulonglong2*)(bk + 8);
            const ulonglong2 b3 = *(const ulonglong2*)(bk + 12);
            const ull bp[8] = {b0.x, b0.y, b1.x, b1.y, b2.x, b2.y, b3.x, b3.y};

            #pragma unroll
            for (int mp = 0; mp < 8; mp++)
                #pragma unroll
                for (int j = 0; j < 8; j++)
                    acc[mp][j] = ffma2(ap[mp], bp[j], acc[mp][j]);
        }
    }

    // Epilogue: acc[mp][j] = (c[tr*16+2mp][j], c[tr*16+2mp+1][j])
    const int colb = bn + tc * 8;
    float bv[8];
    #pragma unroll
    for (int j = 0; j < 8; j++) bv[j] = bias[colb + j];

    #pragma unroll
    for (int mp = 0; mp < 8; mp++) {
        float r0[8], r1[8];
        #pragma unroll
        for (int j = 0; j < 8; j++) {
            float lo, hi;
            unpack2(acc[mp][j], lo, hi);
            r0[j] = lo + bv[j];
            r1[j] = hi + bv[j];
        }
        const int row = bm + tr * 16 + mp * 2;
        float* d0 = g_cur1 + (size_t)row * H_DIM + colb;
        float* d1 = d0 + H_DIM;
        *(float4*)(d0)     = make_float4(r0[0], r0[1], r0[2], r0[3]);
        *(float4*)(d0 + 4) = make_float4(r0[4], r0[5], r0[6], r0[7]);
        *(float4*)(d1)     = make_float4(r1[0], r1[1], r1[2], r1[3]);
        *(float4*)(d1 + 4) = make_float4(r1[4], r1[5], r1[6], r1[7]);
    }
}

// ---------------------------------------------------------------------------
// Phase A: mem1 scan, one thread per (b,h); ballot bitmask.
// ---------------------------------------------------------------------------
__global__ __launch_bounds__(256) void phaseA_kernel() {
    const int gid = blockIdx.x * 256 + threadIdx.x;
    const int b = gid >> 10;
    const int h = gid & 1023;
    const int lane = threadIdx.x & 31;

    const float* cp = g_cur1 + (size_t)b * T_STEPS * H_DIM + h;
    unsigned* sp = g_spk + (size_t)b * T_STEPS * 32 + (h >> 5);

    float mem = 0.f, spk = 0.f;
    float c = cp[0];
    for (int t = 0; t < T_STEPS; t++) {
        float cn = (t + 1 < T_STEPS) ? cp[(size_t)(t + 1) * H_DIM] : 0.f;
        mem = fmaf(BETA, mem, c) - spk;
        spk = (mem > 1.0f) ? 1.0f : 0.0f;
        unsigned bal = __ballot_sync(0xffffffffu, mem > 1.0f);
        if (lane == 0) sp[(size_t)t * 32] = bal;
        c = cn;
    }
}

// ---------------------------------------------------------------------------
// Phase B: cur2T[o][m] = sum_h spk[m][h]*w2[o][h], h strictly sequential.
// ---------------------------------------------------------------------------
__global__ __launch_bounds__(256) void phaseB_kernel(const float* __restrict__ w2) {
    __shared__ float w2s[H_DIM * O_DIM];
    for (int i = threadIdx.x; i < H_DIM * O_DIM; i += 256) {
        const int o = i / H_DIM, h = i % H_DIM;
        w2s[h * O_DIM + o] = w2[i];
    }
    __syncthreads();

    const int warp = blockIdx.x * 8 + (threadIdx.x >> 5);
    const int row  = warp * 32 + (threadIdx.x & 31);

    float acc[O_DIM];
    #pragma unroll
    for (int o = 0; o < O_DIM; o++) acc[o] = 0.f;

    const unsigned* sw = g_spk + (size_t)row * 32;
    for (int wb = 0; wb < 32; wb++) {
        const unsigned bits = sw[wb];
        #pragma unroll 8
        for (int j = 0; j < 32; j++) {
            const float f = ((bits >> j) & 1u) ? 1.0f : 0.0f;
            const float* wp = &w2s[(wb * 32 + j) * O_DIM];
            #pragma unroll
            for (int o = 0; o < O_DIM; o++)
                acc[o] = fmaf(f, wp[o], acc[o]);
        }
    }
    #pragma unroll
    for (int o = 0; o < O_DIM; o++)
        g_cur2T[(size_t)o * M_TOTAL + row] = acc[o];
}

// ---------------------------------------------------------------------------
// Phase C: mem2 scan per (b,o); contiguous t-reads from cur2T.
// ---------------------------------------------------------------------------
__global__ void phaseC_kernel(const float* __restrict__ b2,
                              float* __restrict__ out_spk,
                              float* __restrict__ out_mem) {
    const int id = blockIdx.x * 32 + threadIdx.x;
    if (id >= B_SIZE * O_DIM) return;
    const int b = id / O_DIM;
    const int o = id % O_DIM;

    const float bias = b2[o];
    const float* cp = g_cur2T + (size_t)o * M_TOTAL + (size_t)b * T_STEPS;
    float* os = out_spk + (size_t)b * T_STEPS * O_DIM + o;
    float* om = out_mem + (size_t)b * T_STEPS * O_DIM + o;

    float mem = 0.f, spk = 0.f;
    for (int t0 = 0; t0 < T_STEPS; t0 += 8) {
        const float4 v0 = *(const float4*)(cp + t0);
        const float4 v1 = *(const float4*)(cp + t0 + 4);
        const float c[8] = {v0.x, v0.y, v0.z, v0.w, v1.x, v1.y, v1.z, v1.w};
        #pragma unroll
        for (int i = 0; i < 8; i++) {
            mem = fmaf(BETA, mem, c[i] + bias) - spk;
            spk = (mem > 1.0f) ? 1.0f : 0.0f;
            os[(size_t)(t0 + i) * O_DIM] = spk;
            om[(size_t)(t0 + i) * O_DIM] = mem;
        }
    }
}

// ---------------------------------------------------------------------------
extern "C" void kernel_launch(void* const* d_in, const int* in_sizes, int n_in,
                              void* d_out, int out_size)
{
    const float* x  = (const float*)d_in[0];
    const float* w1 = (const float*)d_in[1];
    const float* b1 = (const float*)d_in[2];
    const float* w2 = (const float*)d_in[3];
    const float* b2 = (const float*)d_in[4];
    float* out = (float*)d_out;

    dim3 gg(H_DIM / BNg, M_TOTAL / BMg);        // (8, 200) = 1600 CTAs
    gemm1_ffma2<<<gg, 128>>>(x, w1, b1);

    phaseA_kernel<<<(B_SIZE * H_DIM) / 256, 256>>>();
    phaseB_kernel<<<M_TOTAL / 256, 256>>>(w2);
    phaseC_kernel<<<(B_SIZE * O_DIM + 31) / 32, 32>>>(
        b2, out, out + (size_t)B_SIZE * T_STEPS * O_DIM);
}